// round 15
// baseline (speedup 1.0000x reference)
#include <cuda_runtime.h>
#include <cuda_fp16.h>
#include <cstdint>

typedef unsigned int u32;
typedef long long ll;

#define Ss 4096
#define Hh 1024
#define MT (4 * Ss)

// ---------------- scratch ----------------
__device__ __align__(256) __half g_xhi[(size_t)MT * Hh];
__device__ __align__(256) __half g_wh[3][(size_t)Hh * Hh];     // Wq,Wk,Wv fp16
__device__ __align__(256) __half g_qkvhi[3][(size_t)MT * Hh];  // q,k,v fp16
__device__ __align__(256) __half g_e[(size_t)4 * Ss * Ss];     // energy fp16
__device__ __align__(256) __half g_phi[(size_t)4 * Ss * Ss];

// ---------------- helpers ----------------
__device__ __forceinline__ u32 s2u(const void* p) {
    u32 a;
    asm("{ .reg .u64 t; cvta.to.shared.u64 t, %1; cvt.u32.u64 %0, t; }" : "=r"(a) : "l"(p));
    return a;
}
__device__ __forceinline__ void cp16(u32 dst, const void* src) {
    asm volatile("cp.async.cg.shared.global [%0], [%1], 16;" :: "r"(dst), "l"(src) : "memory");
}
#define CP_COMMIT() asm volatile("cp.async.commit_group;" ::: "memory")
#define CP_WAIT1()  asm volatile("cp.async.wait_group 1;" ::: "memory")
#define CP_WAIT0()  asm volatile("cp.async.wait_group 0;" ::: "memory")

#define LDSM4(R, addr) \
    asm volatile("ldmatrix.sync.aligned.m8n8.x4.shared.b16 {%0,%1,%2,%3}, [%4];" \
        : "=r"((R)[0]), "=r"((R)[1]), "=r"((R)[2]), "=r"((R)[3]) : "r"(addr))
#define LDSM4T(R, addr) \
    asm volatile("ldmatrix.sync.aligned.m8n8.x4.trans.shared.b16 {%0,%1,%2,%3}, [%4];" \
        : "=r"((R)[0]), "=r"((R)[1]), "=r"((R)[2]), "=r"((R)[3]) : "r"(addr))

#define MMA_(d, a, b) \
    asm volatile("mma.sync.aligned.m16n8k16.row.col.f32.f16.f16.f32 " \
        "{%0,%1,%2,%3},{%4,%5,%6,%7},{%8,%9},{%0,%1,%2,%3};" \
        : "+f"((d)[0]), "+f"((d)[1]), "+f"((d)[2]), "+f"((d)[3]) \
        : "r"((a)[0]), "r"((a)[1]), "r"((a)[2]), "r"((a)[3]), "r"((b)[0]), "r"((b)[1]))

// ---------------- SMEM: K-chunk 64, 2 operand slots/stage, 3 stages, 2 CTAs/SM ----------------
// NT operand: 128 rows x 64 halves, pitch 72 halves (144B) -> 18432 B
// NN operand: 64 rows x 128 halves, pitch 136 halves (272B) -> 17408 B (fits 18432 slot)
#define OPB  18432
#define STGB (2 * OPB)     // 36864
#define SMEMB (3 * STGB)   // 110592
#define NTHR 128

__device__ __forceinline__ void ld_nt(u32 dst, const __half* g, int ld, int r0, int k0, int tid) {
#pragma unroll
    for (int i = 0; i < 8; i++) {
        int q = tid + (i << 7);
        int r = q >> 3, c = q & 7;
        cp16(dst + (u32)(r * 144 + c * 16), g + (size_t)(r0 + r) * ld + k0 + c * 8);
    }
}
__device__ __forceinline__ void ld_nn(u32 dst, const __half* g, int ld, int n0, int k0, int tid) {
#pragma unroll
    for (int i = 0; i < 8; i++) {
        int q = tid + (i << 7);
        int r = q >> 4, c = q & 15;
        cp16(dst + (u32)(r * 272 + c * 16), g + (size_t)(k0 + r) * ld + n0 + c * 8);
    }
}

// -------- HMMA GEMM: C = scale*(Ah @ op(Bh)) [+ bias], fp16 operands, fp32 accum --------
// CTA 128x128, 4 warps (2M x 2N), warp tile 64x64, 128 threads, 2 CTAs/SM.
// BNN=0: B [N,K] (B^T). BNN=1: B [K,N].
// OUTM=0: fp16*scale (energy). OUTM=1: fp16 + bias (proj). OUTM=2: fp32 (final out).
template <int BNN, int OUTM>
__global__ __launch_bounds__(NTHR, 2)
void gemm_mma(const __half* __restrict__ Ah, int lda, ll sA,
              const __half* __restrict__ Bh, int ldb, ll sB,
              const float* __restrict__ b0, const float* __restrict__ b1,
              const float* __restrict__ b2, float scale,
              float* __restrict__ Cf, __half* __restrict__ Chi,
              int ldc, ll sC, int K)
{
    extern __shared__ __align__(16) char smc[];
    const u32 sb = s2u(smc);
    const int tid = threadIdx.x, wid = tid >> 5, lid = tid & 31;
    const int wm = wid >> 1, wn = wid & 1;
    const int m0 = blockIdx.y * 128, n0 = blockIdx.x * 128, z = blockIdx.z;

    const __half* pAh = Ah + (ll)z * sA;
    const __half* pBh = Bh + (ll)z * sB;
    const float* bias = (z == 0) ? b0 : ((z == 1) ? b1 : b2);

    float acc[128];
#pragma unroll
    for (int i = 0; i < 128; i++) acc[i] = 0.0f;

    const int nc = K >> 6;

    const int aRow = wm * 64 + (lid & 15);
    const int aColS = (lid >> 4) << 3;
    int bRow, bColS;
    if (BNN) { bRow = (lid & 7) + (((lid >> 3) & 1) << 3); bColS = wn * 64 + ((lid >> 4) << 3); }
    else     { bRow = wn * 64 + (lid & 7) + ((lid >> 4) << 3); bColS = ((lid >> 3) & 1) << 3; }

    // prologue: stages 0,1 <- chunks 0,1
#pragma unroll
    for (int j = 0; j < 2; j++) {
        u32 bs = sb + (u32)j * STGB;
        int k0 = j << 6;
        ld_nt(bs, pAh, lda, m0, k0, tid);
        if (BNN) ld_nn(bs + OPB, pBh, ldb, n0, k0, tid);
        else     ld_nt(bs + OPB, pBh, ldb, n0, k0, tid);
        CP_COMMIT();
    }

    int stg = 0;
    for (int j = 0; j < nc; j++) {
        if (j + 2 < nc) CP_WAIT1(); else CP_WAIT0();
        __syncthreads();
        if (j + 2 < nc) {
            int s2 = (j + 2) % 3;
            u32 bs = sb + (u32)s2 * STGB;
            int k0 = (j + 2) << 6;
            ld_nt(bs, pAh, lda, m0, k0, tid);
            if (BNN) ld_nn(bs + OPB, pBh, ldb, n0, k0, tid);
            else     ld_nt(bs + OPB, pBh, ldb, n0, k0, tid);
            CP_COMMIT();
        }
        const u32 sS = sb + (u32)stg * STGB;
        const u32 sAh = sS, sBh = sS + OPB;

#pragma unroll
        for (int kk = 0; kk < 4; kk++) {
            const int kb = kk << 4;
            u32 ah[16], bb[16];
#pragma unroll
            for (int mi = 0; mi < 4; mi++)
                LDSM4(ah + mi * 4, sAh + (u32)(((aRow + mi * 16) * 72 + kb + aColS) * 2));
#pragma unroll
            for (int p4 = 0; p4 < 4; p4++) {
                if (BNN) LDSM4T(bb + p4 * 4, sBh + (u32)(((kb + bRow) * 136 + bColS + p4 * 16) * 2));
                else     LDSM4(bb + p4 * 4, sBh + (u32)(((bRow + p4 * 16) * 72 + kb + bColS) * 2));
            }
#pragma unroll
            for (int mi = 0; mi < 4; mi++)
#pragma unroll
                for (int nj = 0; nj < 8; nj++) MMA_(acc + (mi * 8 + nj) * 4, ah + mi * 4, bb + nj * 2);
        }
        stg = (stg + 1) % 3;
    }

    // -------- epilogue --------
    const int g = lid >> 2, t4 = lid & 3;
#pragma unroll
    for (int mi = 0; mi < 4; mi++) {
#pragma unroll
        for (int nj = 0; nj < 8; nj++) {
            const float* c = acc + (mi * 8 + nj) * 4;
            int row = m0 + wm * 64 + mi * 16 + g;
            int col = n0 + wn * 64 + nj * 8 + t4 * 2;
            if (OUTM == 2) {
                size_t base = (size_t)((ll)z * sC) + (size_t)row * ldc + col;
                *(float2*)&Cf[base] = make_float2(c[0] * scale, c[1] * scale);
                *(float2*)&Cf[base + 8 * (size_t)ldc] = make_float2(c[2] * scale, c[3] * scale);
            } else if (OUTM == 0) {
                size_t o = (size_t)((ll)z * sC) + (size_t)row * ldc + col;
                *(__half2*)&Chi[o] = __floats2half2_rn(c[0] * scale, c[1] * scale);
                o += 8 * (size_t)ldc;
                *(__half2*)&Chi[o] = __floats2half2_rn(c[2] * scale, c[3] * scale);
            } else {
                float bb0 = bias[col], bb1 = bias[col + 1];
                size_t o = (size_t)((ll)z * sC) + (size_t)row * ldc + col;
                *(__half2*)&Chi[o] = __floats2half2_rn(c[0] + bb0, c[1] + bb1);
                o += 8 * (size_t)ldc;
                *(__half2*)&Chi[o] = __floats2half2_rn(c[2] + bb0, c[3] + bb1);
            }
        }
    }
}

// ---------------- elementwise ----------------
__global__ void conv_hi(const float* __restrict__ in, __half* __restrict__ hi) {
    size_t i = (size_t)blockIdx.x * blockDim.x + threadIdx.x;
    float4 v = ((const float4*)in)[i];
    ((__half2*)hi)[2 * i]     = __floats2half2_rn(v.x, v.y);
    ((__half2*)hi)[2 * i + 1] = __floats2half2_rn(v.z, v.w);
}

__global__ void conv_w3(const float* __restrict__ w0, const float* __restrict__ w1,
                        const float* __restrict__ w2, __half* __restrict__ wout) {
    const int sel = blockIdx.y;
    const float* in = (sel == 0) ? w0 : ((sel == 1) ? w1 : w2);
    __half* hi = wout + (size_t)sel * Hh * Hh;
    size_t i = (size_t)blockIdx.x * blockDim.x + threadIdx.x;
    float4 v = ((const float4*)in)[i];
    ((__half2*)hi)[2 * i]     = __floats2half2_rn(v.x, v.y);
    ((__half2*)hi)[2 * i + 1] = __floats2half2_rn(v.z, v.w);
}

// softmax over fp16 energy row -> fp16 probabilities
__global__ void softmax_h(const __half* __restrict__ e, __half* __restrict__ phi) {
    const size_t row = blockIdx.x;
    const uint4* p = (const uint4*)(e + row * Ss);   // 512 x 8 halves
    const int t = threadIdx.x;
    float f[16];
    float mx = -1e30f;
#pragma unroll
    for (int c = 0; c < 2; c++) {
        uint4 v = p[t + c * 256];
        const __half2* h = (const __half2*)&v;
#pragma unroll
        for (int u = 0; u < 4; u++) {
            float2 w = __half22float2(h[u]);
            f[c * 8 + u * 2]     = w.x;
            f[c * 8 + u * 2 + 1] = w.y;
            mx = fmaxf(mx, fmaxf(w.x, w.y));
        }
    }
    __shared__ float red[256];
    red[t] = mx; __syncthreads();
    for (int s = 128; s > 0; s >>= 1) { if (t < s) red[t] = fmaxf(red[t], red[t + s]); __syncthreads(); }
    mx = red[0]; __syncthreads();
    float sum = 0.0f;
#pragma unroll
    for (int i = 0; i < 16; i++) { f[i] = __expf(f[i] - mx); sum += f[i]; }
    red[t] = sum; __syncthreads();
    for (int s = 128; s > 0; s >>= 1) { if (t < s) red[t] += red[t + s]; __syncthreads(); }
    const float inv = 1.0f / red[0];
    uint4* ph = (uint4*)(phi + row * Ss);
#pragma unroll
    for (int c = 0; c < 2; c++) {
        uint4 o;
        __half2* h = (__half2*)&o;
#pragma unroll
        for (int u = 0; u < 4; u++)
            h[u] = __floats2half2_rn(f[c * 8 + u * 2] * inv, f[c * 8 + u * 2 + 1] * inv);
        ph[t + c * 256] = o;
    }
}

// ---------------- host ----------------
extern "C" void kernel_launch(void* const* d_in, const int* in_sizes, int n_in,
                              void* d_out, int out_size)
{
    const float* x  = (const float*)d_in[0];
    const float* Wq = (const float*)d_in[1];
    const float* bq = (const float*)d_in[2];
    const float* Wk = (const float*)d_in[3];
    const float* bk = (const float*)d_in[4];
    const float* Wv = (const float*)d_in[5];
    const float* bv = (const float*)d_in[6];
    float* out = (float*)d_out;

    __half *xhi, *wh, *qkvhi, *e, *phi;
    cudaGetSymbolAddress((void**)&xhi, g_xhi);
    cudaGetSymbolAddress((void**)&wh,  g_wh);
    cudaGetSymbolAddress((void**)&qkvhi, g_qkvhi);
    cudaGetSymbolAddress((void**)&e,   g_e);
    cudaGetSymbolAddress((void**)&phi, g_phi);

    cudaFuncSetAttribute(gemm_mma<1, 1>, cudaFuncAttributeMaxDynamicSharedMemorySize, SMEMB);
    cudaFuncSetAttribute(gemm_mma<0, 0>, cudaFuncAttributeMaxDynamicSharedMemorySize, SMEMB);
    cudaFuncSetAttribute(gemm_mma<1, 2>, cudaFuncAttributeMaxDynamicSharedMemorySize, SMEMB);

    const size_t HH = (size_t)Hh * Hh;
    const size_t QKV = (size_t)MT * Hh;

    conv_hi<<<(size_t)MT * Hh / 1024, 256>>>(x, xhi);
    conv_w3<<<dim3(HH / 1024, 3), 256>>>(Wq, Wk, Wv, wh);

    // merged projections (B NN): q,k,v = x_h @ W_h + b (fp16 out)
    gemm_mma<1, 1><<<dim3(8, 128, 3), NTHR, SMEMB>>>(
        xhi, Hh, 0,
        wh, Hh, (ll)HH,
        bq, bk, bv, 1.0f,
        nullptr, qkvhi, Hh, (ll)QKV, Hh);

    // energy = Q_h @ K_h^T / 32 (B NT), fp16 out, per-batch
    gemm_mma<0, 0><<<dim3(32, 32, 4), NTHR, SMEMB>>>(
        qkvhi, Hh, (ll)Ss * Hh,
        qkvhi + QKV, Hh, (ll)Ss * Hh,
        nullptr, nullptr, nullptr, 1.0f / 32.0f,
        nullptr, e, Ss, (ll)Ss * Ss, Hh);

    softmax_h<<<MT, 256>>>(e, phi);

    // out = P_h @ V_h (B NN), fp32 out, per-batch
    gemm_mma<1, 2><<<dim3(8, 32, 4), NTHR, SMEMB>>>(
        phi, Ss, (ll)Ss * Ss,
        qkvhi + 2 * QKV, Hh, (ll)Ss * Hh,
        nullptr, nullptr, nullptr, 1.0f,
        out, nullptr, Hh, (ll)Ss * Hh, Ss);
}

// round 16
// speedup vs baseline: 1.0161x; 1.0161x over previous
#include <cuda_runtime.h>
#include <cuda_fp16.h>
#include <cstdint>

typedef unsigned int u32;
typedef long long ll;

#define Ss 4096
#define Hh 1024
#define MT (4 * Ss)

// ---------------- scratch ----------------
__device__ __align__(256) __half g_xhi[(size_t)MT * Hh];
__device__ __align__(256) __half g_wh[3][(size_t)Hh * Hh];     // Wq,Wk,Wv fp16
__device__ __align__(256) __half g_qkvhi[3][(size_t)MT * Hh];  // q,k,v fp16
__device__ __align__(256) __half g_e[(size_t)4 * Ss * Ss];     // energy fp16
__device__ __align__(256) __half g_phi[(size_t)4 * Ss * Ss];

// ---------------- helpers ----------------
__device__ __forceinline__ u32 s2u(const void* p) {
    u32 a;
    asm("{ .reg .u64 t; cvta.to.shared.u64 t, %1; cvt.u32.u64 %0, t; }" : "=r"(a) : "l"(p));
    return a;
}
__device__ __forceinline__ void cp16(u32 dst, const void* src) {
    asm volatile("cp.async.cg.shared.global [%0], [%1], 16;" :: "r"(dst), "l"(src) : "memory");
}
#define CP_COMMIT() asm volatile("cp.async.commit_group;" ::: "memory")
#define CP_WAIT1()  asm volatile("cp.async.wait_group 1;" ::: "memory")
#define CP_WAIT0()  asm volatile("cp.async.wait_group 0;" ::: "memory")

#define LDSM4(R, addr) \
    asm volatile("ldmatrix.sync.aligned.m8n8.x4.shared.b16 {%0,%1,%2,%3}, [%4];" \
        : "=r"((R)[0]), "=r"((R)[1]), "=r"((R)[2]), "=r"((R)[3]) : "r"(addr))
#define LDSM4T(R, addr) \
    asm volatile("ldmatrix.sync.aligned.m8n8.x4.trans.shared.b16 {%0,%1,%2,%3}, [%4];" \
        : "=r"((R)[0]), "=r"((R)[1]), "=r"((R)[2]), "=r"((R)[3]) : "r"(addr))

#define MMA_(d, a, b) \
    asm volatile("mma.sync.aligned.m16n8k16.row.col.f32.f16.f16.f32 " \
        "{%0,%1,%2,%3},{%4,%5,%6,%7},{%8,%9},{%0,%1,%2,%3};" \
        : "+f"((d)[0]), "+f"((d)[1]), "+f"((d)[2]), "+f"((d)[3]) \
        : "r"((a)[0]), "r"((a)[1]), "r"((a)[2]), "r"((a)[3]), "r"((b)[0]), "r"((b)[1]))

// ---------------- SMEM: K-chunk 64, 2 operand slots/stage, 3 stages, 2 CTAs/SM ----------------
// NT operand: 128 rows x 64 halves, pitch 72 halves (144B) -> 18432 B
// NN operand: 64 rows x 128 halves, pitch 136 halves (272B) -> 17408 B (fits 18432 slot)
#define OPB  18432
#define STGB (2 * OPB)     // 36864
#define SMEMB (3 * STGB)   // 110592

__device__ __forceinline__ void ld_nt(u32 dst, const __half* g, int ld, int r0, int k0, int tid) {
#pragma unroll
    for (int i = 0; i < 4; i++) {
        int q = tid + (i << 8);
        int r = q >> 3, c = q & 7;
        cp16(dst + (u32)(r * 144 + c * 16), g + (size_t)(r0 + r) * ld + k0 + c * 8);
    }
}
__device__ __forceinline__ void ld_nn(u32 dst, const __half* g, int ld, int n0, int k0, int tid) {
#pragma unroll
    for (int i = 0; i < 4; i++) {
        int q = tid + (i << 8);
        int r = q >> 4, c = q & 15;
        cp16(dst + (u32)(r * 272 + c * 16), g + (size_t)(k0 + r) * ld + n0 + c * 8);
    }
}

// -------- HMMA GEMM: C = scale*(Ah @ op(Bh)) [+ bias], fp16 operands, fp32 accum --------
// CTA 128x128, warps 4(M) x 2(N), warp tile 32x64, 256 threads, 2 CTAs/SM.
// BNN=0: B [N,K] (B^T). BNN=1: B [K,N].
// OUTM=0: fp16*scale (energy). OUTM=1: fp16 + bias (proj). OUTM=2: fp32 (final out).
template <int BNN, int OUTM>
__global__ __launch_bounds__(256, 2)
void gemm_mma(const __half* __restrict__ Ah, int lda, ll sA,
              const __half* __restrict__ Bh, int ldb, ll sB,
              const float* __restrict__ b0, const float* __restrict__ b1,
              const float* __restrict__ b2, float scale,
              float* __restrict__ Cf, __half* __restrict__ Chi,
              int ldc, ll sC, int K)
{
    extern __shared__ __align__(16) char smc[];
    const u32 sb = s2u(smc);
    const int tid = threadIdx.x, wid = tid >> 5, lid = tid & 31;
    const int wm = wid >> 1, wn = wid & 1;
    const int m0 = blockIdx.y * 128, n0 = blockIdx.x * 128, z = blockIdx.z;

    const __half* pAh = Ah + (ll)z * sA;
    const __half* pBh = Bh + (ll)z * sB;
    const float* bias = (z == 0) ? b0 : ((z == 1) ? b1 : b2);

    float acc[64];
#pragma unroll
    for (int i = 0; i < 64; i++) acc[i] = 0.0f;

    const int nc = K >> 6;

    const int aRow = wm * 32 + (lid & 15);
    const int aColS = (lid >> 4) << 3;
    int bRow, bColS;
    if (BNN) { bRow = (lid & 7) + (((lid >> 3) & 1) << 3); bColS = wn * 64 + ((lid >> 4) << 3); }
    else     { bRow = wn * 64 + (lid & 7) + ((lid >> 4) << 3); bColS = ((lid >> 3) & 1) << 3; }

    // prologue: stages 0,1 <- chunks 0,1
#pragma unroll
    for (int j = 0; j < 2; j++) {
        u32 bs = sb + (u32)j * STGB;
        int k0 = j << 6;
        ld_nt(bs, pAh, lda, m0, k0, tid);
        if (BNN) ld_nn(bs + OPB, pBh, ldb, n0, k0, tid);
        else     ld_nt(bs + OPB, pBh, ldb, n0, k0, tid);
        CP_COMMIT();
    }

    int stg = 0;
    for (int j = 0; j < nc; j++) {
        if (j + 2 < nc) CP_WAIT1(); else CP_WAIT0();
        __syncthreads();
        const u32 sS = sb + (u32)stg * STGB;
        const u32 sAh = sS, sBh = sS + OPB;
        const bool pf = (j + 2 < nc);
        const int s2 = (j + 2) % 3;
        const u32 bs = sb + (u32)s2 * STGB;
        const int kp = (j + 2) << 6;

        // issue A-prefetch, then start kk=0 fragment loads (drain LDS latency),
        // then B-prefetch, then rest of compute.
        if (pf) ld_nt(bs, pAh, lda, m0, kp, tid);

        u32 ah[8], bb[16];
#pragma unroll
        for (int mi = 0; mi < 2; mi++)
            LDSM4(ah + mi * 4, sAh + (u32)(((aRow + mi * 16) * 72 + aColS) * 2));
#pragma unroll
        for (int p4 = 0; p4 < 4; p4++) {
            if (BNN) LDSM4T(bb + p4 * 4, sBh + (u32)((bRow * 136 + bColS + p4 * 16) * 2));
            else     LDSM4(bb + p4 * 4, sBh + (u32)(((bRow + p4 * 16) * 72 + bColS) * 2));
        }

        if (pf) {
            if (BNN) ld_nn(bs + OPB, pBh, ldb, n0, kp, tid);
            else     ld_nt(bs + OPB, pBh, ldb, n0, kp, tid);
            CP_COMMIT();
        }

#pragma unroll
        for (int mi = 0; mi < 2; mi++)
#pragma unroll
            for (int nj = 0; nj < 8; nj++) MMA_(acc + (mi * 8 + nj) * 4, ah + mi * 4, bb + nj * 2);

#pragma unroll
        for (int kk = 1; kk < 4; kk++) {
            const int kb = kk << 4;
#pragma unroll
            for (int mi = 0; mi < 2; mi++)
                LDSM4(ah + mi * 4, sAh + (u32)(((aRow + mi * 16) * 72 + kb + aColS) * 2));
#pragma unroll
            for (int p4 = 0; p4 < 4; p4++) {
                if (BNN) LDSM4T(bb + p4 * 4, sBh + (u32)(((kb + bRow) * 136 + bColS + p4 * 16) * 2));
                else     LDSM4(bb + p4 * 4, sBh + (u32)(((bRow + p4 * 16) * 72 + kb + bColS) * 2));
            }
#pragma unroll
            for (int mi = 0; mi < 2; mi++)
#pragma unroll
                for (int nj = 0; nj < 8; nj++) MMA_(acc + (mi * 8 + nj) * 4, ah + mi * 4, bb + nj * 2);
        }
        stg = (stg + 1) % 3;
    }

    // -------- epilogue --------
    const int g = lid >> 2, t4 = lid & 3;
#pragma unroll
    for (int mi = 0; mi < 2; mi++) {
#pragma unroll
        for (int nj = 0; nj < 8; nj++) {
            const float* c = acc + (mi * 8 + nj) * 4;
            int row = m0 + wm * 32 + mi * 16 + g;
            int col = n0 + wn * 64 + nj * 8 + t4 * 2;
            if (OUTM == 2) {
                size_t base = (size_t)((ll)z * sC) + (size_t)row * ldc + col;
                *(float2*)&Cf[base] = make_float2(c[0] * scale, c[1] * scale);
                *(float2*)&Cf[base + 8 * (size_t)ldc] = make_float2(c[2] * scale, c[3] * scale);
            } else if (OUTM == 0) {
                size_t o = (size_t)((ll)z * sC) + (size_t)row * ldc + col;
                *(__half2*)&Chi[o] = __floats2half2_rn(c[0] * scale, c[1] * scale);
                o += 8 * (size_t)ldc;
                *(__half2*)&Chi[o] = __floats2half2_rn(c[2] * scale, c[3] * scale);
            } else {
                float bb0 = bias[col], bb1 = bias[col + 1];
                size_t o = (size_t)((ll)z * sC) + (size_t)row * ldc + col;
                *(__half2*)&Chi[o] = __floats2half2_rn(c[0] + bb0, c[1] + bb1);
                o += 8 * (size_t)ldc;
                *(__half2*)&Chi[o] = __floats2half2_rn(c[2] + bb0, c[3] + bb1);
            }
        }
    }
}

// ---------------- elementwise ----------------
// merged fp32->fp16 conversion: z=0 -> x (16 MB-blocks), z=1..3 -> Wq,Wk,Wv
__global__ void conv_all(const float* __restrict__ x,
                         const float* __restrict__ w0, const float* __restrict__ w1,
                         const float* __restrict__ w2,
                         __half* __restrict__ xhi, __half* __restrict__ wh) {
    const int sel = blockIdx.y;
    const float* in;
    __half* outp;
    if (sel == 0) { in = x; outp = xhi; }
    else { in = (sel == 1) ? w0 : ((sel == 2) ? w1 : w2); outp = wh + (size_t)(sel - 1) * Hh * Hh; }
    size_t n4 = (sel == 0) ? ((size_t)MT * Hh / 4) : ((size_t)Hh * Hh / 4);
    for (size_t i = (size_t)blockIdx.x * blockDim.x + threadIdx.x; i < n4;
         i += (size_t)gridDim.x * blockDim.x) {
        float4 v = ((const float4*)in)[i];
        ((__half2*)outp)[2 * i]     = __floats2half2_rn(v.x, v.y);
        ((__half2*)outp)[2 * i + 1] = __floats2half2_rn(v.z, v.w);
    }
}

// softmax over fp16 energy row -> fp16 probabilities (512 threads, 8 halves/thread)
__global__ void softmax_h(const __half* __restrict__ e, __half* __restrict__ phi) {
    const size_t row = blockIdx.x;
    const uint4* p = (const uint4*)(e + row * Ss);
    const int t = threadIdx.x;
    float f[8];
    float mx = -1e30f;
    {
        uint4 v = p[t];
        const __half2* h = (const __half2*)&v;
#pragma unroll
        for (int u = 0; u < 4; u++) {
            float2 w = __half22float2(h[u]);
            f[u * 2] = w.x; f[u * 2 + 1] = w.y;
            mx = fmaxf(mx, fmaxf(w.x, w.y));
        }
    }
    __shared__ float red[512];
    red[t] = mx; __syncthreads();
    for (int s = 256; s > 0; s >>= 1) { if (t < s) red[t] = fmaxf(red[t], red[t + s]); __syncthreads(); }
    mx = red[0]; __syncthreads();
    float sum = 0.0f;
#pragma unroll
    for (int i = 0; i < 8; i++) { f[i] = __expf(f[i] - mx); sum += f[i]; }
    red[t] = sum; __syncthreads();
    for (int s = 256; s > 0; s >>= 1) { if (t < s) red[t] += red[t + s]; __syncthreads(); }
    const float inv = 1.0f / red[0];
    uint4 o;
    __half2* h = (__half2*)&o;
#pragma unroll
    for (int u = 0; u < 4; u++)
        h[u] = __floats2half2_rn(f[u * 2] * inv, f[u * 2 + 1] * inv);
    ((uint4*)(phi + row * Ss))[t] = o;
}

// ---------------- host ----------------
extern "C" void kernel_launch(void* const* d_in, const int* in_sizes, int n_in,
                              void* d_out, int out_size)
{
    const float* x  = (const float*)d_in[0];
    const float* Wq = (const float*)d_in[1];
    const float* bq = (const float*)d_in[2];
    const float* Wk = (const float*)d_in[3];
    const float* bk = (const float*)d_in[4];
    const float* Wv = (const float*)d_in[5];
    const float* bv = (const float*)d_in[6];
    float* out = (float*)d_out;

    __half *xhi, *wh, *qkvhi, *e, *phi;
    cudaGetSymbolAddress((void**)&xhi, g_xhi);
    cudaGetSymbolAddress((void**)&wh,  g_wh);
    cudaGetSymbolAddress((void**)&qkvhi, g_qkvhi);
    cudaGetSymbolAddress((void**)&e,   g_e);
    cudaGetSymbolAddress((void**)&phi, g_phi);

    cudaFuncSetAttribute(gemm_mma<1, 1>, cudaFuncAttributeMaxDynamicSharedMemorySize, SMEMB);
    cudaFuncSetAttribute(gemm_mma<0, 0>, cudaFuncAttributeMaxDynamicSharedMemorySize, SMEMB);
    cudaFuncSetAttribute(gemm_mma<1, 2>, cudaFuncAttributeMaxDynamicSharedMemorySize, SMEMB);

    const size_t HH = (size_t)Hh * Hh;
    const size_t QKV = (size_t)MT * Hh;

    // merged conversions (z=0: x, z=1..3: weights)
    conv_all<<<dim3(1024, 4), 256>>>(x, Wq, Wk, Wv, xhi, wh);

    // merged projections (B NN): q,k,v = x_h @ W_h + b (fp16 out)
    gemm_mma<1, 1><<<dim3(8, 128, 3), 256, SMEMB>>>(
        xhi, Hh, 0,
        wh, Hh, (ll)HH,
        bq, bk, bv, 1.0f,
        nullptr, qkvhi, Hh, (ll)QKV, Hh);

    // energy = Q_h @ K_h^T / 32 (B NT), fp16 out, per-batch
    gemm_mma<0, 0><<<dim3(32, 32, 4), 256, SMEMB>>>(
        qkvhi, Hh, (ll)Ss * Hh,
        qkvhi + QKV, Hh, (ll)Ss * Hh,
        nullptr, nullptr, nullptr, 1.0f / 32.0f,
        nullptr, e, Ss, (ll)Ss * Ss, Hh);

    softmax_h<<<MT, 512>>>(e, phi);

    // out = P_h @ V_h (B NN), fp32 out, per-batch
    gemm_mma<1, 2><<<dim3(8, 32, 4), 256, SMEMB>>>(
        phi, Ss, (ll)Ss * Ss,
        qkvhi + 2 * QKV, Hh, (ll)Ss * Hh,
        nullptr, nullptr, nullptr, 1.0f,
        out, nullptr, Hh, (ll)Ss * Hh, Ss);
}